// round 4
// baseline (speedup 1.0000x reference)
#include <cuda_runtime.h>
#include <math.h>

#define BS    8
#define NROT  60
#define NPTS  500
#define NBR   (BS * NROT)     // 480
#define NHALF (2 * NBR)       // 960 chamfer half-blocks
#define HW    6400            // 80*80
#define NPAIR 250             // NPTS/2 target pairs

typedef unsigned long long u64;

// Scratch (allocation-free: __device__ globals)
__device__ float g_symp[NHALF];     // partial sym sums (per half-block)
__device__ float g_nonsymp[NHALF];  // partial nonsym sums
__device__ float g_scal[2];         // [0] = loss_reg, [1] = loss_t
__device__ unsigned int g_cnt;      // completion counter (reset by last block)

// ---- f32x2 packed helpers (FFMA2 path; sm_103a) ----------------------------
__device__ __forceinline__ u64 pack2(float a, float b) {
    u64 r; asm("mov.b64 %0, {%1, %2};" : "=l"(r) : "f"(a), "f"(b)); return r;
}
__device__ __forceinline__ u64 fma2(u64 a, u64 b, u64 c) {
    u64 d; asm("fma.rn.f32x2 %0, %1, %2, %3;" : "=l"(d) : "l"(a), "l"(b), "l"(c));
    return d;
}
__device__ __forceinline__ void unpack2(u64 v, float& lo, float& hi) {
    asm("mov.b64 {%0, %1}, %2;" : "=f"(lo), "=f"(hi) : "l"(v));
}

// ---------------------------------------------------------------------------
// Single fused kernel, grid = NHALF + 1 blocks of 128 threads.
//  blocks 0..959 : chamfer for half of one (b, r): 250 pred points, all targets
//  block  960    : reg loss + huber translation loss (runs concurrently)
//  last block to finish: finalize loss_r and combine into out[0..3]
// ---------------------------------------------------------------------------
__global__ __launch_bounds__(128) void fused_kernel(
    const float* __restrict__ pred_t,        // (8,500,3)
    const float* __restrict__ pred_r,        // (8,60,4)
    const float* __restrict__ pred_c,        // (8,60)
    const float* __restrict__ target_r,      // (8,1,500,3)
    const float* __restrict__ target_t,      // (8,3,80,80)
    const float* __restrict__ model_points,  // (8,1,500,3)
    const int*   __restrict__ choose,        // (8,500)
    const int*   __restrict__ symmetric,     // (8,) bool->int32
    const float* __restrict__ diameters,     // (8,)
    const float* __restrict__ rot_anchors,   // (60,4)
    float*       __restrict__ out)           // 4 floats
{
    __shared__ float4 sA[NPAIR];   // (-2tx[m0], -2tx[m1], -2ty[m0], -2ty[m1])
    __shared__ float4 sB[NPAIR];   // (-2tz[m0], -2tz[m1], |t0|^2,   |t1|^2)
    __shared__ float  redA[4], redB[4];
    __shared__ int    s_last;

    const int tid  = threadIdx.x;
    const int lane = tid & 31;
    const int wid  = tid >> 5;
    const int blk  = blockIdx.x;

    if (blk < NHALF) {
        // ================= chamfer half-block =================
        const int br   = blk >> 1;
        const int half = blk & 1;
        const int b    = br / NROT;
        const int base = half * 250;
        const float* tp = target_r + (size_t)b * NPTS * 3;

        for (int j = tid; j < NPAIR; j += 128) {
            int m0 = 2 * j, m1 = m0 + 1;
            float t0x = tp[3*m0], t0y = tp[3*m0+1], t0z = tp[3*m0+2];
            float t1x = tp[3*m1], t1y = tp[3*m1+1], t1z = tp[3*m1+2];
            sA[j] = make_float4(-2.f*t0x, -2.f*t1x, -2.f*t0y, -2.f*t1y);
            sB[j] = make_float4(-2.f*t0z, -2.f*t1z,
                                t0x*t0x + t0y*t0y + t0z*t0z,
                                t1x*t1x + t1y*t1y + t1z*t1z);
        }

        // Rotation matrix from (unnormalized) quaternion, as reference.
        const float* q = pred_r + (size_t)br * 4;
        float w = q[0], x = q[1], y = q[2], z = q[3];
        float r00 = 1.f - 2.f*(y*y + z*z);
        float r01 = 2.f*x*y - 2.f*w*z;
        float r02 = 2.f*w*y + 2.f*x*z;
        float r10 = 2.f*x*y + 2.f*z*w;
        float r11 = 1.f - 2.f*(x*x + z*z);
        float r12 = -2.f*w*x + 2.f*y*z;
        float r20 = -2.f*w*y + 2.f*x*z;
        float r21 = 2.f*w*x + 2.f*y*z;
        float r22 = 1.f - 2.f*(x*x + y*y);

        __syncthreads();

        // 2 pred points per thread: n = base + tid, base + tid + 128
        const float* mpb = model_points + (size_t)b * NPTS * 3;
        float px[2], py[2], pz[2], a2[2];
        bool  val[2];
        u64   PX[2], PY[2], PZ[2];
        #pragma unroll
        for (int i = 0; i < 2; i++) {
            int l = tid + 128 * i;          // local point idx within half (0..249)
            int n = base + l;
            val[i] = (l < 250);
            float mx = 0.f, my = 0.f, mz = 0.f;
            if (val[i]) { mx = mpb[3*n]; my = mpb[3*n+1]; mz = mpb[3*n+2]; }
            px[i] = r00*mx + r01*my + r02*mz;
            py[i] = r10*mx + r11*my + r12*mz;
            pz[i] = r20*mx + r21*my + r22*mz;
            a2[i] = px[i]*px[i] + py[i]*py[i] + pz[i]*pz[i];
            PX[i] = pack2(px[i], px[i]);
            PY[i] = pack2(py[i], py[i]);
            PZ[i] = pack2(pz[i], pz[i]);
        }

        const float INF = 3.4e38f;
        float mnlo[2] = {INF, INF};
        float mnhi[2] = {INF, INF};

        #pragma unroll 5
        for (int j = 0; j < NPAIR; j++) {
            ulonglong2 va = *reinterpret_cast<const ulonglong2*>(&sA[j]); // X, Y
            ulonglong2 vb = *reinterpret_cast<const ulonglong2*>(&sB[j]); // Z, W
            #pragma unroll
            for (int i = 0; i < 2; i++) {
                u64 s = fma2(PX[i], va.x, fma2(PY[i], va.y, fma2(PZ[i], vb.x, vb.y)));
                float lo, hi; unpack2(s, lo, hi);
                mnlo[i] = fminf(mnlo[i], lo);
                mnhi[i] = fminf(mnhi[i], hi);
            }
        }

        float symsum = 0.f, nssum = 0.f;
        #pragma unroll
        for (int i = 0; i < 2; i++) {
            if (val[i]) {
                float mn = fminf(mnlo[i], mnhi[i]);
                symsum += sqrtf(fmaxf(a2[i] + mn, 1e-12f));
                int n = base + tid + 128 * i;
                float dx = px[i] - tp[3*n];
                float dy = py[i] - tp[3*n+1];
                float dz = pz[i] - tp[3*n+2];
                nssum += sqrtf(dx*dx + dy*dy + dz*dz);
            }
        }

        #pragma unroll
        for (int off = 16; off; off >>= 1) {
            symsum += __shfl_down_sync(0xffffffffu, symsum, off);
            nssum  += __shfl_down_sync(0xffffffffu, nssum,  off);
        }
        if (lane == 0) { redA[wid] = symsum; redB[wid] = nssum; }
        __syncthreads();
        if (tid == 0) {
            g_symp[blk]    = redA[0] + redA[1] + redA[2] + redA[3];
            g_nonsymp[blk] = redB[0] + redB[1] + redB[2] + redB[3];
        }
    } else {
        // ================= reg + huber block =================
        float* anc = reinterpret_cast<float*>(sA);  // 240 floats
        for (int i = tid; i < NROT * 4; i += 128) anc[i] = rot_anchors[i];
        __syncthreads();

        float regsum = 0.f;
        for (int i = tid; i < NBR; i += 128) {
            int r = i % NROT;
            float q0 = pred_r[4*i], q1 = pred_r[4*i+1];
            float q2 = pred_r[4*i+2], q3 = pred_r[4*i+3];
            float mx = -3.4e38f, dg = 0.f;
            #pragma unroll 4
            for (int a = 0; a < NROT; a++) {
                float c = q0*anc[4*a] + q1*anc[4*a+1] + q2*anc[4*a+2] + q3*anc[4*a+3];
                mx = fmaxf(mx, c);
                if (a == r) dg = c;
            }
            float reg = mx - dg;
            regsum += (reg > 0.001f) ? reg : 0.f;
        }

        float tsum = 0.f;
        for (int i = tid; i < BS * NPTS; i += 128) {
            int b  = i / NPTS;
            int ch = choose[i];
            const float* tb = target_t + (size_t)b * 3 * HW;
            float tv0 = tb[ch], tv1 = tb[HW + ch], tv2 = tb[2*HW + ch];
            float p0 = pred_t[3*i], p1 = pred_t[3*i+1], p2 = pred_t[3*i+2];
            float d0 = p0 - tv0, d1 = p1 - tv1, d2 = p2 - tv2;
            float a0 = fabsf(d0), a1 = fabsf(d1), a2v = fabsf(d2);
            tsum += (a0 < 1.f) ? 0.5f*d0*d0 : (a0 - 0.5f);
            tsum += (a1 < 1.f) ? 0.5f*d1*d1 : (a1 - 0.5f);
            tsum += (a2v < 1.f) ? 0.5f*d2*d2 : (a2v - 0.5f);
        }

        #pragma unroll
        for (int off = 16; off; off >>= 1) {
            regsum += __shfl_down_sync(0xffffffffu, regsum, off);
            tsum   += __shfl_down_sync(0xffffffffu, tsum,   off);
        }
        if (lane == 0) { redA[wid] = regsum; redB[wid] = tsum; }
        __syncthreads();
        if (tid == 0) {
            g_scal[0] = (redA[0]+redA[1]+redA[2]+redA[3]) * (1.0f / NBR);
            g_scal[1] = (redB[0]+redB[1]+redB[2]+redB[3]) * (1.0f / (BS*NPTS*3));
        }
    }

    // ================= grid-completion: last block finalizes =================
    __threadfence();
    if (tid == 0) {
        unsigned int ticket = atomicAdd(&g_cnt, 1u);
        s_last = (ticket == (unsigned)(NHALF + 1) - 1u) ? 1 : 0;
    }
    __syncthreads();

    if (s_last) {
        float lr = 0.f;
        for (int i = tid; i < NBR; i += 128) {
            int b = i / NROT;
            float sym_d    = (g_symp[2*i]    + g_symp[2*i+1])    * (1.0f / NPTS);
            float nonsym_d = (g_nonsymp[2*i] + g_nonsymp[2*i+1]) * (1.0f / NPTS);
            float d = (symmetric[b] != 0) ? sym_d : nonsym_d;
            float c = pred_c[i];
            lr += (d / (diameters[b] * c) + logf(c)) * (1.0f / NROT);
        }
        #pragma unroll
        for (int off = 16; off; off >>= 1)
            lr += __shfl_down_sync(0xffffffffu, lr, off);
        if (lane == 0) redA[wid] = lr;
        __syncthreads();
        if (tid == 0) {
            float lrt  = redA[0] + redA[1] + redA[2] + redA[3];
            float lreg = g_scal[0];
            float lt   = g_scal[1];
            out[0] = lrt + 2.f * lreg + 5.f * lt;
            out[1] = lrt;
            out[2] = lreg;
            out[3] = lt;
            g_cnt = 0;   // reset for next graph replay
        }
    }
}

// ---------------------------------------------------------------------------
// Launch. Input order: pred_t, pred_r, pred_c, target_r, target_t,
//                      model_points, choose, symmetric, diameters, rot_anchors
// ---------------------------------------------------------------------------
extern "C" void kernel_launch(void* const* d_in, const int* in_sizes, int n_in,
                              void* d_out, int out_size)
{
    fused_kernel<<<NHALF + 1, 128>>>(
        (const float*)d_in[0], (const float*)d_in[1], (const float*)d_in[2],
        (const float*)d_in[3], (const float*)d_in[4], (const float*)d_in[5],
        (const int*)d_in[6],   (const int*)d_in[7],   (const float*)d_in[8],
        (const float*)d_in[9], (float*)d_out);
}

// round 5
// speedup vs baseline: 1.0048x; 1.0048x over previous
#include <cuda_runtime.h>
#include <math.h>

#define BS    8
#define NROT  60
#define NPTS  500
#define NBR   (BS * NROT)     // 480
#define HW    6400            // 80*80
#define NPAIR 250             // NPTS/2 target pairs
#define CHUNK 5               // j-iterations batched per load group (250 = 5*50)

typedef unsigned long long u64;

// Scratch (allocation-free: __device__ globals)
__device__ float g_sym[NBR];
__device__ float g_nonsym[NBR];
__device__ float g_scal[2];       // [0] = loss_reg, [1] = loss_t
__device__ unsigned int g_cnt;    // completion counter (reset by last block)

// ---- f32x2 packed helpers (FFMA2 path; sm_103a) ----------------------------
__device__ __forceinline__ u64 pack2(float a, float b) {
    u64 r; asm("mov.b64 %0, {%1, %2};" : "=l"(r) : "f"(a), "f"(b)); return r;
}
__device__ __forceinline__ u64 fma2(u64 a, u64 b, u64 c) {
    u64 d; asm("fma.rn.f32x2 %0, %1, %2, %3;" : "=l"(d) : "l"(a), "l"(b), "l"(c));
    return d;
}
__device__ __forceinline__ void unpack2(u64 v, float& lo, float& hi) {
    asm("mov.b64 {%0, %1}, %2;" : "=f"(lo), "=f"(hi) : "l"(v));
}

// ---------------------------------------------------------------------------
// Single fused kernel, grid = NBR + 1 blocks of 128 threads.
//  blocks 0..479 : chamfer for one (b, r); 4 pred points per thread
//  block  480    : reg loss + huber translation loss (runs concurrently)
//  last block to finish: finalize loss_r and combine into out[0..3]
// ---------------------------------------------------------------------------
__global__ __launch_bounds__(128, 3) void fused_kernel(
    const float* __restrict__ pred_t,        // (8,500,3)
    const float* __restrict__ pred_r,        // (8,60,4)
    const float* __restrict__ pred_c,        // (8,60)
    const float* __restrict__ target_r,      // (8,1,500,3)
    const float* __restrict__ target_t,      // (8,3,80,80)
    const float* __restrict__ model_points,  // (8,1,500,3)
    const int*   __restrict__ choose,        // (8,500)
    const int*   __restrict__ symmetric,     // (8,) bool->int32
    const float* __restrict__ diameters,     // (8,)
    const float* __restrict__ rot_anchors,   // (60,4)
    float*       __restrict__ out)           // 4 floats
{
    __shared__ float4 sA[NPAIR];   // (-2tx[m0], -2tx[m1], -2ty[m0], -2ty[m1])
    __shared__ float4 sB[NPAIR];   // (-2tz[m0], -2tz[m1], |t0|^2,   |t1|^2)
    __shared__ float  redA[4], redB[4];
    __shared__ int    s_last;

    const int tid  = threadIdx.x;
    const int lane = tid & 31;
    const int wid  = tid >> 5;
    const int blk  = blockIdx.x;

    if (blk < NBR) {
        // ================= chamfer block =================
        const int b = blk / NROT;
        const float* tp = target_r + (size_t)b * NPTS * 3;

        for (int j = tid; j < NPAIR; j += 128) {
            int m0 = 2 * j, m1 = m0 + 1;
            float t0x = tp[3*m0], t0y = tp[3*m0+1], t0z = tp[3*m0+2];
            float t1x = tp[3*m1], t1y = tp[3*m1+1], t1z = tp[3*m1+2];
            sA[j] = make_float4(-2.f*t0x, -2.f*t1x, -2.f*t0y, -2.f*t1y);
            sB[j] = make_float4(-2.f*t0z, -2.f*t1z,
                                t0x*t0x + t0y*t0y + t0z*t0z,
                                t1x*t1x + t1y*t1y + t1z*t1z);
        }

        // Rotation matrix from (unnormalized) quaternion, as reference.
        const float* q = pred_r + (size_t)blk * 4;
        float w = q[0], x = q[1], y = q[2], z = q[3];
        float r00 = 1.f - 2.f*(y*y + z*z);
        float r01 = 2.f*x*y - 2.f*w*z;
        float r02 = 2.f*w*y + 2.f*x*z;
        float r10 = 2.f*x*y + 2.f*z*w;
        float r11 = 1.f - 2.f*(x*x + z*z);
        float r12 = -2.f*w*x + 2.f*y*z;
        float r20 = -2.f*w*y + 2.f*x*z;
        float r21 = 2.f*w*x + 2.f*y*z;
        float r22 = 1.f - 2.f*(x*x + y*y);

        __syncthreads();

        // 4 pred points per thread: n = tid + 128*i
        const float* mpb = model_points + (size_t)b * NPTS * 3;
        float px[4], py[4], pz[4], a2[4];
        bool  val[4];
        u64   PX[4], PY[4], PZ[4];
        #pragma unroll
        for (int i = 0; i < 4; i++) {
            int n = tid + 128 * i;
            val[i] = (n < NPTS);
            float mx = 0.f, my = 0.f, mz = 0.f;
            if (val[i]) { mx = mpb[3*n]; my = mpb[3*n+1]; mz = mpb[3*n+2]; }
            px[i] = r00*mx + r01*my + r02*mz;
            py[i] = r10*mx + r11*my + r12*mz;
            pz[i] = r20*mx + r21*my + r22*mz;
            a2[i] = px[i]*px[i] + py[i]*py[i] + pz[i]*pz[i];
            PX[i] = pack2(px[i], px[i]);
            PY[i] = pack2(py[i], py[i]);
            PZ[i] = pack2(pz[i], pz[i]);
        }

        const float INF = 3.4e38f;
        float mnlo[4] = {INF, INF, INF, INF};
        float mnhi[4] = {INF, INF, INF, INF};

        const ulonglong2* A = reinterpret_cast<const ulonglong2*>(sA);
        const ulonglong2* Bv = reinterpret_cast<const ulonglong2*>(sB);

        // Chunked: batch 2*CHUNK LDS.128 (MLP ~10), then 12*CHUNK FFMA2.
        for (int j0 = 0; j0 < NPAIR; j0 += CHUNK) {
            ulonglong2 va[CHUNK], vb[CHUNK];
            #pragma unroll
            for (int k = 0; k < CHUNK; k++) { va[k] = A[j0+k]; vb[k] = Bv[j0+k]; }
            #pragma unroll
            for (int k = 0; k < CHUNK; k++) {
                #pragma unroll
                for (int i = 0; i < 4; i++) {
                    u64 s = fma2(PX[i], va[k].x,
                             fma2(PY[i], va[k].y,
                              fma2(PZ[i], vb[k].x, vb[k].y)));
                    float lo, hi; unpack2(s, lo, hi);
                    mnlo[i] = fminf(mnlo[i], lo);
                    mnhi[i] = fminf(mnhi[i], hi);
                }
            }
        }

        float symsum = 0.f, nssum = 0.f;
        #pragma unroll
        for (int i = 0; i < 4; i++) {
            if (val[i]) {
                float mn = fminf(mnlo[i], mnhi[i]);
                symsum += sqrtf(fmaxf(a2[i] + mn, 1e-12f));
                int n = tid + 128 * i;
                float dx = px[i] - tp[3*n];
                float dy = py[i] - tp[3*n+1];
                float dz = pz[i] - tp[3*n+2];
                nssum += sqrtf(dx*dx + dy*dy + dz*dz);
            }
        }

        #pragma unroll
        for (int off = 16; off; off >>= 1) {
            symsum += __shfl_down_sync(0xffffffffu, symsum, off);
            nssum  += __shfl_down_sync(0xffffffffu, nssum,  off);
        }
        if (lane == 0) { redA[wid] = symsum; redB[wid] = nssum; }
        __syncthreads();
        if (tid == 0) {
            g_sym[blk]    = (redA[0]+redA[1]+redA[2]+redA[3]) * (1.0f / NPTS);
            g_nonsym[blk] = (redB[0]+redB[1]+redB[2]+redB[3]) * (1.0f / NPTS);
        }
    } else {
        // ================= reg + huber block =================
        float* anc = reinterpret_cast<float*>(sA);  // 240 floats
        for (int i = tid; i < NROT * 4; i += 128) anc[i] = rot_anchors[i];
        __syncthreads();

        float regsum = 0.f;
        for (int i = tid; i < NBR; i += 128) {
            int r = i % NROT;
            float q0 = pred_r[4*i], q1 = pred_r[4*i+1];
            float q2 = pred_r[4*i+2], q3 = pred_r[4*i+3];
            float mx = -3.4e38f, dg = 0.f;
            #pragma unroll 4
            for (int a = 0; a < NROT; a++) {
                float c = q0*anc[4*a] + q1*anc[4*a+1] + q2*anc[4*a+2] + q3*anc[4*a+3];
                mx = fmaxf(mx, c);
                if (a == r) dg = c;
            }
            float reg = mx - dg;
            regsum += (reg > 0.001f) ? reg : 0.f;
        }

        float tsum = 0.f;
        for (int i = tid; i < BS * NPTS; i += 128) {
            int b  = i / NPTS;
            int ch = choose[i];
            const float* tb = target_t + (size_t)b * 3 * HW;
            float tv0 = tb[ch], tv1 = tb[HW + ch], tv2 = tb[2*HW + ch];
            float p0 = pred_t[3*i], p1 = pred_t[3*i+1], p2 = pred_t[3*i+2];
            float d0 = p0 - tv0, d1 = p1 - tv1, d2 = p2 - tv2;
            float a0 = fabsf(d0), a1 = fabsf(d1), a2v = fabsf(d2);
            tsum += (a0 < 1.f) ? 0.5f*d0*d0 : (a0 - 0.5f);
            tsum += (a1 < 1.f) ? 0.5f*d1*d1 : (a1 - 0.5f);
            tsum += (a2v < 1.f) ? 0.5f*d2*d2 : (a2v - 0.5f);
        }

        #pragma unroll
        for (int off = 16; off; off >>= 1) {
            regsum += __shfl_down_sync(0xffffffffu, regsum, off);
            tsum   += __shfl_down_sync(0xffffffffu, tsum,   off);
        }
        if (lane == 0) { redA[wid] = regsum; redB[wid] = tsum; }
        __syncthreads();
        if (tid == 0) {
            g_scal[0] = (redA[0]+redA[1]+redA[2]+redA[3]) * (1.0f / NBR);
            g_scal[1] = (redB[0]+redB[1]+redB[2]+redB[3]) * (1.0f / (BS*NPTS*3));
        }
    }

    // ================= grid-completion: last block finalizes =================
    __threadfence();
    if (tid == 0) {
        unsigned int ticket = atomicAdd(&g_cnt, 1u);
        s_last = (ticket == (unsigned)(NBR + 1) - 1u) ? 1 : 0;
    }
    __syncthreads();

    if (s_last) {
        float lr = 0.f;
        for (int i = tid; i < NBR; i += 128) {
            int b = i / NROT;
            float d = (symmetric[b] != 0) ? g_sym[i] : g_nonsym[i];
            float c = pred_c[i];
            lr += (d / (diameters[b] * c) + logf(c)) * (1.0f / NROT);
        }
        #pragma unroll
        for (int off = 16; off; off >>= 1)
            lr += __shfl_down_sync(0xffffffffu, lr, off);
        if (lane == 0) redA[wid] = lr;
        __syncthreads();
        if (tid == 0) {
            float lrt  = redA[0] + redA[1] + redA[2] + redA[3];
            float lreg = g_scal[0];
            float lt   = g_scal[1];
            out[0] = lrt + 2.f * lreg + 5.f * lt;
            out[1] = lrt;
            out[2] = lreg;
            out[3] = lt;
            g_cnt = 0;   // reset for next graph replay
        }
    }
}

// ---------------------------------------------------------------------------
// Launch. Input order: pred_t, pred_r, pred_c, target_r, target_t,
//                      model_points, choose, symmetric, diameters, rot_anchors
// ---------------------------------------------------------------------------
extern "C" void kernel_launch(void* const* d_in, const int* in_sizes, int n_in,
                              void* d_out, int out_size)
{
    fused_kernel<<<NBR + 1, 128>>>(
        (const float*)d_in[0], (const float*)d_in[1], (const float*)d_in[2],
        (const float*)d_in[3], (const float*)d_in[4], (const float*)d_in[5],
        (const int*)d_in[6],   (const int*)d_in[7],   (const float*)d_in[8],
        (const float*)d_in[9], (float*)d_out);
}

// round 7
// speedup vs baseline: 1.0683x; 1.0632x over previous
#include <cuda_runtime.h>
#include <math.h>

#define BS    8
#define NROT  60
#define NPTS  500
#define NBR   (BS * NROT)     // 480
#define HW    6400            // 80*80
#define NPAIR 250             // NPTS/2 target pairs
#define CHUNK 5               // j-iterations batched per load group (250 = 5*50)
#define TPB   256             // threads per block
#define NW    (TPB / 32)      // warps per block

typedef unsigned long long u64;

// Scratch (allocation-free: __device__ globals)
__device__ float g_sym[NBR];
__device__ float g_nonsym[NBR];
__device__ float g_scal[2];       // [0] = loss_reg, [1] = loss_t
__device__ unsigned int g_cnt;    // completion counter (reset by last block)

// ---- f32x2 packed helpers (FFMA2 path; sm_103a) ----------------------------
__device__ __forceinline__ u64 pack2(float a, float b) {
    u64 r; asm("mov.b64 %0, {%1, %2};" : "=l"(r) : "f"(a), "f"(b)); return r;
}
__device__ __forceinline__ u64 fma2(u64 a, u64 b, u64 c) {
    u64 d; asm("fma.rn.f32x2 %0, %1, %2, %3;" : "=l"(d) : "l"(a), "l"(b), "l"(c));
    return d;
}
__device__ __forceinline__ void unpack2(u64 v, float& lo, float& hi) {
    asm("mov.b64 {%0, %1}, %2;" : "=f"(lo), "=f"(hi) : "l"(v));  // free: reg pair alias
}

// ---------------------------------------------------------------------------
// Single fused kernel, grid = NBR + 1 blocks of 256 threads.
//  blocks 0..479 : chamfer for one (b, r); 2 pred points per thread
//  block  480    : reg loss + huber translation loss (runs concurrently)
//  last block to finish: finalize loss_r and combine into out[0..3]
// ---------------------------------------------------------------------------
__global__ __launch_bounds__(TPB, 4) void fused_kernel(
    const float* __restrict__ pred_t,        // (8,500,3)
    const float* __restrict__ pred_r,        // (8,60,4)
    const float* __restrict__ pred_c,        // (8,60)
    const float* __restrict__ target_r,      // (8,1,500,3)
    const float* __restrict__ target_t,      // (8,3,80,80)
    const float* __restrict__ model_points,  // (8,1,500,3)
    const int*   __restrict__ choose,        // (8,500)
    const int*   __restrict__ symmetric,     // (8,) bool->int32
    const float* __restrict__ diameters,     // (8,)
    const float* __restrict__ rot_anchors,   // (60,4)
    float*       __restrict__ out)           // 4 floats
{
    __shared__ float4 sA[NPAIR];   // (-2tx[m0], -2tx[m1], -2ty[m0], -2ty[m1])
    __shared__ float4 sB[NPAIR];   // (-2tz[m0], -2tz[m1], |t0|^2,   |t1|^2)
    __shared__ float  redA[NW], redB[NW];
    __shared__ int    s_last;

    const int tid  = threadIdx.x;
    const int lane = tid & 31;
    const int wid  = tid >> 5;
    const int blk  = blockIdx.x;

    if (blk < NBR) {
        // ================= chamfer block =================
        const int b = blk / NROT;
        const float* tp = target_r + (size_t)b * NPTS * 3;

        for (int j = tid; j < NPAIR; j += TPB) {
            int m0 = 2 * j, m1 = m0 + 1;
            float t0x = tp[3*m0], t0y = tp[3*m0+1], t0z = tp[3*m0+2];
            float t1x = tp[3*m1], t1y = tp[3*m1+1], t1z = tp[3*m1+2];
            sA[j] = make_float4(-2.f*t0x, -2.f*t1x, -2.f*t0y, -2.f*t1y);
            sB[j] = make_float4(-2.f*t0z, -2.f*t1z,
                                t0x*t0x + t0y*t0y + t0z*t0z,
                                t1x*t1x + t1y*t1y + t1z*t1z);
        }

        // Rotation matrix from (unnormalized) quaternion, as reference.
        const float* q = pred_r + (size_t)blk * 4;
        float w = q[0], x = q[1], y = q[2], z = q[3];
        float r00 = 1.f - 2.f*(y*y + z*z);
        float r01 = 2.f*x*y - 2.f*w*z;
        float r02 = 2.f*w*y + 2.f*x*z;
        float r10 = 2.f*x*y + 2.f*z*w;
        float r11 = 1.f - 2.f*(x*x + z*z);
        float r12 = -2.f*w*x + 2.f*y*z;
        float r20 = -2.f*w*y + 2.f*x*z;
        float r21 = 2.f*w*x + 2.f*y*z;
        float r22 = 1.f - 2.f*(x*x + y*y);

        __syncthreads();

        // 2 pred points per thread: n = tid, tid + 256
        const float* mpb = model_points + (size_t)b * NPTS * 3;
        float px[2], py[2], pz[2], a2[2];
        bool  val[2];
        u64   PX[2], PY[2], PZ[2];
        #pragma unroll
        for (int i = 0; i < 2; i++) {
            int n = tid + TPB * i;
            val[i] = (n < NPTS);
            float mx = 0.f, my = 0.f, mz = 0.f;
            if (val[i]) { mx = mpb[3*n]; my = mpb[3*n+1]; mz = mpb[3*n+2]; }
            px[i] = r00*mx + r01*my + r02*mz;
            py[i] = r10*mx + r11*my + r12*mz;
            pz[i] = r20*mx + r21*my + r22*mz;
            a2[i] = px[i]*px[i] + py[i]*py[i] + pz[i]*pz[i];
            PX[i] = pack2(px[i], px[i]);
            PY[i] = pack2(py[i], py[i]);
            PZ[i] = pack2(pz[i], pz[i]);
        }

        const float INF = 3.4e38f;
        float mnlo[2] = {INF, INF};
        float mnhi[2] = {INF, INF};

        const ulonglong2* A  = reinterpret_cast<const ulonglong2*>(sA);
        const ulonglong2* Bv = reinterpret_cast<const ulonglong2*>(sB);

        // Inner loop per j: 2 LDS.128 (amortized) + 6 fma2 + 4 FMNMX.
        for (int j0 = 0; j0 < NPAIR; j0 += CHUNK) {
            ulonglong2 va[CHUNK], vb[CHUNK];
            #pragma unroll
            for (int k = 0; k < CHUNK; k++) { va[k] = A[j0+k]; vb[k] = Bv[j0+k]; }
            #pragma unroll
            for (int k = 0; k < CHUNK; k++) {
                #pragma unroll
                for (int i = 0; i < 2; i++) {
                    u64 s = fma2(PX[i], va[k].x,
                             fma2(PY[i], va[k].y,
                              fma2(PZ[i], vb[k].x, vb[k].y)));
                    float lo, hi; unpack2(s, lo, hi);
                    mnlo[i] = fminf(mnlo[i], lo);
                    mnhi[i] = fminf(mnhi[i], hi);
                }
            }
        }

        float symsum = 0.f, nssum = 0.f;
        #pragma unroll
        for (int i = 0; i < 2; i++) {
            if (val[i]) {
                float m = fminf(mnlo[i], mnhi[i]);
                symsum += sqrtf(fmaxf(a2[i] + m, 1e-12f));
                int n = tid + TPB * i;
                float dx = px[i] - tp[3*n];
                float dy = py[i] - tp[3*n+1];
                float dz = pz[i] - tp[3*n+2];
                nssum += sqrtf(dx*dx + dy*dy + dz*dz);
            }
        }

        #pragma unroll
        for (int off = 16; off; off >>= 1) {
            symsum += __shfl_down_sync(0xffffffffu, symsum, off);
            nssum  += __shfl_down_sync(0xffffffffu, nssum,  off);
        }
        if (lane == 0) { redA[wid] = symsum; redB[wid] = nssum; }
        __syncthreads();
        if (tid == 0) {
            float sa = 0.f, sb = 0.f;
            #pragma unroll
            for (int k = 0; k < NW; k++) { sa += redA[k]; sb += redB[k]; }
            g_sym[blk]    = sa * (1.0f / NPTS);
            g_nonsym[blk] = sb * (1.0f / NPTS);
        }
    } else {
        // ================= reg + huber block =================
        float* anc = reinterpret_cast<float*>(sA);  // 240 floats
        for (int i = tid; i < NROT * 4; i += TPB) anc[i] = rot_anchors[i];
        __syncthreads();

        float regsum = 0.f;
        for (int i = tid; i < NBR; i += TPB) {
            int r = i % NROT;
            float q0 = pred_r[4*i], q1 = pred_r[4*i+1];
            float q2 = pred_r[4*i+2], q3 = pred_r[4*i+3];
            float mx = -3.4e38f, dg = 0.f;
            #pragma unroll 4
            for (int a = 0; a < NROT; a++) {
                float c = q0*anc[4*a] + q1*anc[4*a+1] + q2*anc[4*a+2] + q3*anc[4*a+3];
                mx = fmaxf(mx, c);
                if (a == r) dg = c;
            }
            float reg = mx - dg;
            regsum += (reg > 0.001f) ? reg : 0.f;
        }

        float tsum = 0.f;
        for (int i = tid; i < BS * NPTS; i += TPB) {
            int b  = i / NPTS;
            int ch = choose[i];
            const float* tb = target_t + (size_t)b * 3 * HW;
            float tv0 = tb[ch], tv1 = tb[HW + ch], tv2 = tb[2*HW + ch];
            float p0 = pred_t[3*i], p1 = pred_t[3*i+1], p2 = pred_t[3*i+2];
            float d0 = p0 - tv0, d1 = p1 - tv1, d2 = p2 - tv2;
            float a0 = fabsf(d0), a1 = fabsf(d1), a2v = fabsf(d2);
            tsum += (a0 < 1.f) ? 0.5f*d0*d0 : (a0 - 0.5f);
            tsum += (a1 < 1.f) ? 0.5f*d1*d1 : (a1 - 0.5f);
            tsum += (a2v < 1.f) ? 0.5f*d2*d2 : (a2v - 0.5f);
        }

        #pragma unroll
        for (int off = 16; off; off >>= 1) {
            regsum += __shfl_down_sync(0xffffffffu, regsum, off);
            tsum   += __shfl_down_sync(0xffffffffu, tsum,   off);
        }
        if (lane == 0) { redA[wid] = regsum; redB[wid] = tsum; }
        __syncthreads();
        if (tid == 0) {
            float sa = 0.f, sb = 0.f;
            #pragma unroll
            for (int k = 0; k < NW; k++) { sa += redA[k]; sb += redB[k]; }
            g_scal[0] = sa * (1.0f / NBR);
            g_scal[1] = sb * (1.0f / (BS*NPTS*3));
        }
    }

    // ================= grid-completion: last block finalizes =================
    __threadfence();
    if (tid == 0) {
        unsigned int ticket = atomicAdd(&g_cnt, 1u);
        s_last = (ticket == (unsigned)(NBR + 1) - 1u) ? 1 : 0;
    }
    __syncthreads();

    if (s_last) {
        float lr = 0.f;
        for (int i = tid; i < NBR; i += TPB) {
            int b = i / NROT;
            float d = (symmetric[b] != 0) ? g_sym[i] : g_nonsym[i];
            float c = pred_c[i];
            lr += (d / (diameters[b] * c) + logf(c)) * (1.0f / NROT);
        }
        #pragma unroll
        for (int off = 16; off; off >>= 1)
            lr += __shfl_down_sync(0xffffffffu, lr, off);
        if (lane == 0) redA[wid] = lr;
        __syncthreads();
        if (tid == 0) {
            float lrt = 0.f;
            #pragma unroll
            for (int k = 0; k < NW; k++) lrt += redA[k];
            float lreg = g_scal[0];
            float lt   = g_scal[1];
            out[0] = lrt + 2.f * lreg + 5.f * lt;
            out[1] = lrt;
            out[2] = lreg;
            out[3] = lt;
            g_cnt = 0;   // reset for next graph replay
        }
    }
}

// ---------------------------------------------------------------------------
// Launch. Input order: pred_t, pred_r, pred_c, target_r, target_t,
//                      model_points, choose, symmetric, diameters, rot_anchors
// ---------------------------------------------------------------------------
extern "C" void kernel_launch(void* const* d_in, const int* in_sizes, int n_in,
                              void* d_out, int out_size)
{
    fused_kernel<<<NBR + 1, TPB>>>(
        (const float*)d_in[0], (const float*)d_in[1], (const float*)d_in[2],
        (const float*)d_in[3], (const float*)d_in[4], (const float*)d_in[5],
        (const int*)d_in[6],   (const int*)d_in[7],   (const float*)d_in[8],
        (const float*)d_in[9], (float*)d_out);
}